// round 11
// baseline (speedup 1.0000x reference)
#include <cuda_runtime.h>
#include <math.h>

#define T_TOK 8192
#define DIMM  1024
#define NHEAD 16
#define DHEAD 64
#define NCTX  77
#define BATCH 4
#define SEQ   2048
#define FFI   4096

// ---------------- scratch (device globals: allocation-free) ----------------
__device__ float g_ln  [T_TOK * DIMM];
__device__ float g_q   [T_TOK * DIMM];
__device__ float g_k   [T_TOK * DIMM];
__device__ float g_v   [T_TOK * DIMM];
__device__ float g_attn[T_TOK * DIMM];
__device__ float g_x1  [T_TOK * DIMM];
__device__ float g_x2  [T_TOK * DIMM];
__device__ float g_ffp [(size_t)T_TOK * 8192];
__device__ float g_h   [(size_t)T_TOK * FFI];

// ---------------- packed f32x2 helpers ----------------
__device__ __forceinline__ unsigned long long pk2(float x, float y) {
    unsigned long long r;
    asm("mov.b64 %0, {%1,%2};" : "=l"(r) : "f"(x), "f"(y));
    return r;
}
__device__ __forceinline__ unsigned long long f2u(float2 v) {
    unsigned long long r;
    asm("mov.b64 %0, {%1,%2};" : "=l"(r) : "f"(v.x), "f"(v.y));
    return r;
}
__device__ __forceinline__ void fma2(unsigned long long& d, unsigned long long a,
                                     unsigned long long b) {
    asm("fma.rn.f32x2 %0, %1, %2, %0;" : "+l"(d) : "l"(a), "l"(b));
}
__device__ __forceinline__ unsigned long long mul2(unsigned long long a,
                                                   unsigned long long b) {
    unsigned long long r;
    asm("mul.rn.f32x2 %0, %1, %2;" : "=l"(r) : "l"(a), "l"(b));
    return r;
}
__device__ __forceinline__ float2 u2f(unsigned long long v) {
    float2 r;
    asm("mov.b64 {%0,%1}, %2;" : "=f"(r.x), "=f"(r.y) : "l"(v));
    return r;
}

// ---------------- LayerNorm (1 row per block, 256 threads) ----------------
__global__ __launch_bounds__(256) void ln_kernel(
    const float* __restrict__ x, const float* __restrict__ g,
    const float* __restrict__ be, float* __restrict__ out)
{
    __shared__ float redS[8], redQ[8];
    int row = blockIdx.x, tid = threadIdx.x;
    float4 v = ((const float4*)(x + (size_t)row * DIMM))[tid];
    float s = v.x + v.y + v.z + v.w;
    float q = v.x * v.x + v.y * v.y + v.z * v.z + v.w * v.w;
#pragma unroll
    for (int off = 16; off > 0; off >>= 1) {
        s += __shfl_xor_sync(0xffffffffu, s, off);
        q += __shfl_xor_sync(0xffffffffu, q, off);
    }
    if ((tid & 31) == 0) { redS[tid >> 5] = s; redQ[tid >> 5] = q; }
    __syncthreads();
    float ts = 0.f, tq = 0.f;
#pragma unroll
    for (int w = 0; w < 8; w++) { ts += redS[w]; tq += redQ[w]; }
    float mean = ts * (1.f / 1024.f);
    float var  = tq * (1.f / 1024.f) - mean * mean;
    float rstd = rsqrtf(var + 1e-5f);
    float4 gg = ((const float4*)g)[tid];
    float4 bb = ((const float4*)be)[tid];
    float4 o;
    o.x = (v.x - mean) * rstd * gg.x + bb.x;
    o.y = (v.y - mean) * rstd * gg.y + bb.y;
    o.z = (v.z - mean) * rstd * gg.z + bb.z;
    o.w = (v.w - mean) * rstd * gg.w + bb.w;
    ((float4*)(out + (size_t)row * DIMM))[tid] = o;
}

// ---------------- GEMM: C[MxN] = A[MxK] @ B[KxN] (+bias)(+residual) --------
#define BM 128
#define BN 128
#define BKT 8
#define BSTR 132

template <bool BIAS, bool RES>
__global__ __launch_bounds__(256) void gemm_kernel(
    const float* __restrict__ A, const float* __restrict__ B,
    const float* __restrict__ bias, const float* __restrict__ res,
    float* __restrict__ C, int M, int K, int N)
{
    __shared__ __align__(16) float As[BKT][BM];
    __shared__ __align__(16) float Bs[BKT][BSTR];
    int tid = threadIdx.x;
    int tx = tid & 15, ty = tid >> 4;
    int m0 = blockIdx.y * BM, n0 = blockIdx.x * BN;
    int arow = tid >> 1, acol = (tid & 1) << 2;
    int brow = tid >> 5, bcol = (tid & 31) << 2;
    const float* Ap = A + (size_t)(m0 + arow) * K + acol;
    const float* Bp = B + (size_t)brow * N + n0 + bcol;
    bool aval = (m0 + arow) < M;

    float4 ar = aval ? *(const float4*)Ap : make_float4(0.f, 0.f, 0.f, 0.f);
    float4 br = *(const float4*)Bp;
    As[acol + 0][arow] = ar.x; As[acol + 1][arow] = ar.y;
    As[acol + 2][arow] = ar.z; As[acol + 3][arow] = ar.w;
    *(float4*)&Bs[brow][bcol] = br;
    __syncthreads();

    unsigned long long c2[8][4];
#pragma unroll
    for (int i = 0; i < 8; i++)
#pragma unroll
        for (int j = 0; j < 4; j++) c2[i][j] = 0ULL;

    int nk = K >> 3;
    for (int kt = 0; kt < nk; kt++) {
        if (kt + 1 < nk) {
            ar = aval ? *(const float4*)(Ap + (size_t)(kt + 1) * BKT)
                      : make_float4(0.f, 0.f, 0.f, 0.f);
            br = *(const float4*)(Bp + (size_t)(kt + 1) * BKT * N);
        }
#pragma unroll
        for (int kk = 0; kk < BKT; kk++) {
            float4 a0 = *(const float4*)&As[kk][ty * 8];
            float4 a1 = *(const float4*)&As[kk][ty * 8 + 4];
            float aa[8] = {a0.x, a0.y, a0.z, a0.w, a1.x, a1.y, a1.z, a1.w};
            const float2* bp2 = (const float2*)&Bs[kk][tx * 8];
            unsigned long long bb[4];
#pragma unroll
            for (int j = 0; j < 4; j++) bb[j] = f2u(bp2[j]);
#pragma unroll
            for (int i = 0; i < 8; i++) {
                unsigned long long av = pk2(aa[i], aa[i]);
#pragma unroll
                for (int j = 0; j < 4; j++) fma2(c2[i][j], av, bb[j]);
            }
        }
        __syncthreads();
        if (kt + 1 < nk) {
            As[acol + 0][arow] = ar.x; As[acol + 1][arow] = ar.y;
            As[acol + 2][arow] = ar.z; As[acol + 3][arow] = ar.w;
            *(float4*)&Bs[brow][bcol] = br;
            __syncthreads();
        }
    }

#pragma unroll
    for (int i = 0; i < 8; i++) {
        int m = m0 + ty * 8 + i;
        if (m >= M) continue;
        float* crow = C + (size_t)m * N + n0 + tx * 8;
        const float* rrow = RES ? (res + (size_t)m * N + n0 + tx * 8) : (const float*)0;
#pragma unroll
        for (int j = 0; j < 4; j++) {
            float2 v = u2f(c2[i][j]);
            if (BIAS) {
                v.x += bias[n0 + tx * 8 + 2 * j];
                v.y += bias[n0 + tx * 8 + 2 * j + 1];
            }
            if (RES) { v.x += rrow[2 * j]; v.y += rrow[2 * j + 1]; }
            crow[2 * j]     = v.x;
            crow[2 * j + 1] = v.y;
        }
    }
}

// ---------------- self attention (flash, 64q x 64k tiles) ----------------
#define SKD 66

__global__ __launch_bounds__(256) void attn_self_kernel(
    const float* __restrict__ Q, const float* __restrict__ K,
    const float* __restrict__ V, float* __restrict__ O)
{
    extern __shared__ float sm[];
    float (*Qs)[64]  = (float(*)[64])sm;                             // [q][d]
    float (*Ks)[SKD] = (float(*)[SKD])(sm + 64 * 64);                // [k][d]
    float (*Vs)[SKD] = (float(*)[SKD])(sm + 64 * 64 + 64 * SKD);     // [d][k]
    float (*Ps)[SKD] = (float(*)[SKD])(sm + 64 * 64 + 2 * 64 * SKD); // [q][k]
    int tid = threadIdx.x;
    int tx = tid & 15, ty = tid >> 4;
    int b = blockIdx.z, h = blockIdx.y, qt = blockIdx.x;
    size_t rowbase = (size_t)b * SEQ;
    int col0 = h * DHEAD;

    for (int i = tid; i < 64 * 16; i += 256) {
        int r = i >> 4, dp = (i & 15) << 2;
        *(float4*)&Qs[r][dp] =
            *(const float4*)(Q + (rowbase + qt * 64 + r) * DIMM + col0 + dp);
    }
    int r0 = ty * 4;
    unsigned long long o2[4][4];
#pragma unroll
    for (int i = 0; i < 4; i++)
#pragma unroll
        for (int j = 0; j < 4; j++) o2[i][j] = 0ULL;
    float mrow[4] = {-1e30f, -1e30f, -1e30f, -1e30f};
    float lrow[4] = {0.f, 0.f, 0.f, 0.f};
    const float scale = 0.125f;

    for (int kt = 0; kt < SEQ / 64; kt++) {
        __syncthreads();
        for (int i = tid; i < 64 * 16; i += 256) {
            int c = i >> 4, dp = (i & 15) << 2;
            float4 kv = *(const float4*)(K + (rowbase + kt * 64 + c) * DIMM + col0 + dp);
            Ks[c][dp + 0] = kv.x; Ks[c][dp + 1] = kv.y;
            Ks[c][dp + 2] = kv.z; Ks[c][dp + 3] = kv.w;
            float4 vv = *(const float4*)(V + (rowbase + kt * 64 + c) * DIMM + col0 + dp);
            Vs[dp + 0][c] = vv.x; Vs[dp + 1][c] = vv.y;
            Vs[dp + 2][c] = vv.z; Vs[dp + 3][c] = vv.w;
        }
        __syncthreads();

        unsigned long long s2[4][4];
#pragma unroll
        for (int i = 0; i < 4; i++)
#pragma unroll
            for (int j = 0; j < 4; j++) s2[i][j] = 0ULL;
        for (int d2 = 0; d2 < 32; d2++) {
            unsigned long long q2[4], k2[4];
#pragma unroll
            for (int rr = 0; rr < 4; rr++)
                q2[rr] = f2u(*(const float2*)&Qs[r0 + rr][2 * d2]);
#pragma unroll
            for (int cc = 0; cc < 4; cc++)
                k2[cc] = f2u(*(const float2*)&Ks[tx + 16 * cc][2 * d2]);
#pragma unroll
            for (int rr = 0; rr < 4; rr++)
#pragma unroll
                for (int cc = 0; cc < 4; cc++) fma2(s2[rr][cc], q2[rr], k2[cc]);
        }

#pragma unroll
        for (int rr = 0; rr < 4; rr++) {
            float sv[4];
#pragma unroll
            for (int cc = 0; cc < 4; cc++) {
                float2 t = u2f(s2[rr][cc]);
                sv[cc] = (t.x + t.y) * scale;
            }
            float mx = fmaxf(fmaxf(sv[0], sv[1]), fmaxf(sv[2], sv[3]));
#pragma unroll
            for (int off = 8; off > 0; off >>= 1)
                mx = fmaxf(mx, __shfl_xor_sync(0xffffffffu, mx, off));
            float mnew  = fmaxf(mrow[rr], mx);
            float alpha = __expf(mrow[rr] - mnew);
            mrow[rr] = mnew;
            float psum = 0.f;
#pragma unroll
            for (int cc = 0; cc < 4; cc++) {
                float p = __expf(sv[cc] - mnew);
                Ps[r0 + rr][tx + 16 * cc] = p;
                psum += p;
            }
#pragma unroll
            for (int off = 8; off > 0; off >>= 1)
                psum += __shfl_xor_sync(0xffffffffu, psum, off);
            lrow[rr] = lrow[rr] * alpha + psum;
            unsigned long long a2 = pk2(alpha, alpha);
#pragma unroll
            for (int cc = 0; cc < 4; cc++) o2[rr][cc] = mul2(a2, o2[rr][cc]);
        }
        __syncthreads();

        for (int j2 = 0; j2 < 32; j2++) {
            unsigned long long p2[4], v2[4];
#pragma unroll
            for (int rr = 0; rr < 4; rr++)
                p2[rr] = f2u(*(const float2*)&Ps[r0 + rr][2 * j2]);
#pragma unroll
            for (int cc = 0; cc < 4; cc++)
                v2[cc] = f2u(*(const float2*)&Vs[tx + 16 * cc][2 * j2]);
#pragma unroll
            for (int rr = 0; rr < 4; rr++)
#pragma unroll
                for (int cc = 0; cc < 4; cc++) fma2(o2[rr][cc], p2[rr], v2[cc]);
        }
    }

#pragma unroll
    for (int rr = 0; rr < 4; rr++) {
        float inv = 1.f / lrow[rr];
#pragma unroll
        for (int cc = 0; cc < 4; cc++) {
            float2 t = u2f(o2[rr][cc]);
            O[(rowbase + qt * 64 + r0 + rr) * DIMM + col0 + tx + 16 * cc] =
                (t.x + t.y) * inv;
        }
    }
}

// ---------------- cross attention (77 keys, one pass) ----------------
__global__ __launch_bounds__(256) void attn_cross_kernel(
    const float* __restrict__ Q, const float* __restrict__ K,
    const float* __restrict__ V, float* __restrict__ O)
{
    extern __shared__ float sm[];
    float (*Qs)[64]  = (float(*)[64])sm;                            // [q][d]
    float (*Ks)[SKD] = (float(*)[SKD])(sm + 64 * 64);               // [k][d], 80 rows
    float (*Vs)[SKD] = (float(*)[SKD])(sm + 64 * 64 + 80 * SKD);    // [k][d], 80 rows
    float (*Ps)[80]  = (float(*)[80])(sm + 64 * 64 + 2 * 80 * SKD); // [q][k]
    int tid = threadIdx.x;
    int tx = tid & 15, ty = tid >> 4;
    int b = blockIdx.z, h = blockIdx.y, qt = blockIdx.x;
    size_t rowbase = (size_t)b * SEQ;
    int col0 = h * DHEAD;

    for (int i = tid; i < 64 * 16; i += 256) {
        int r = i >> 4, dp = (i & 15) << 2;
        *(float4*)&Qs[r][dp] =
            *(const float4*)(Q + (rowbase + qt * 64 + r) * DIMM + col0 + dp);
    }
    for (int i = tid; i < 80 * 16; i += 256) {
        int j = i >> 4, dp = (i & 15) << 2;
        float4 kv = make_float4(0.f, 0.f, 0.f, 0.f);
        float4 vv = make_float4(0.f, 0.f, 0.f, 0.f);
        if (j < NCTX) {
            kv = *(const float4*)(K + ((size_t)b * NCTX + j) * DIMM + col0 + dp);
            vv = *(const float4*)(V + ((size_t)b * NCTX + j) * DIMM + col0 + dp);
        }
        Ks[j][dp + 0] = kv.x; Ks[j][dp + 1] = kv.y;
        Ks[j][dp + 2] = kv.z; Ks[j][dp + 3] = kv.w;
        Vs[j][dp + 0] = vv.x; Vs[j][dp + 1] = vv.y;
        Vs[j][dp + 2] = vv.z; Vs[j][dp + 3] = vv.w;
    }
    __syncthreads();

    int r0 = ty * 4;
    float s[4][5];
#pragma unroll
    for (int rr = 0; rr < 4; rr++)
#pragma unroll
        for (int jj = 0; jj < 5; jj++) s[rr][jj] = 0.f;

    for (int d = 0; d < 64; d++) {
        float qv[4], kv[5];
#pragma unroll
        for (int rr = 0; rr < 4; rr++) qv[rr] = Qs[r0 + rr][d];
#pragma unroll
        for (int jj = 0; jj < 5; jj++) kv[jj] = Ks[tx + 16 * jj][d];
#pragma unroll
        for (int rr = 0; rr < 4; rr++)
#pragma unroll
            for (int jj = 0; jj < 5; jj++) s[rr][jj] += qv[rr] * kv[jj];
    }

    const float scale = 0.125f;
#pragma unroll
    for (int rr = 0; rr < 4; rr++) {
        float mx = -1e30f;
#pragma unroll
        for (int jj = 0; jj < 5; jj++) {
            int c = tx + 16 * jj;
            s[rr][jj] *= scale;
            if (c < NCTX) mx = fmaxf(mx, s[rr][jj]);
        }
#pragma unroll
        for (int off = 8; off > 0; off >>= 1)
            mx = fmaxf(mx, __shfl_xor_sync(0xffffffffu, mx, off));
        float sum = 0.f, p[5];
#pragma unroll
        for (int jj = 0; jj < 5; jj++) {
            int c = tx + 16 * jj;
            p[jj] = (c < NCTX) ? __expf(s[rr][jj] - mx) : 0.f;
            sum += p[jj];
        }
#pragma unroll
        for (int off = 8; off > 0; off >>= 1)
            sum += __shfl_xor_sync(0xffffffffu, sum, off);
        float inv = 1.f / sum;
#pragma unroll
        for (int jj = 0; jj < 5; jj++) Ps[r0 + rr][tx + 16 * jj] = p[jj] * inv;
    }
    __syncthreads();

    float o[4][4];
#pragma unroll
    for (int rr = 0; rr < 4; rr++)
#pragma unroll
        for (int cc = 0; cc < 4; cc++) o[rr][cc] = 0.f;
    for (int j = 0; j < NCTX; j++) {
        float pv[4], vv[4];
#pragma unroll
        for (int rr = 0; rr < 4; rr++) pv[rr] = Ps[r0 + rr][j];
#pragma unroll
        for (int cc = 0; cc < 4; cc++) vv[cc] = Vs[j][tx + 16 * cc];
#pragma unroll
        for (int rr = 0; rr < 4; rr++)
#pragma unroll
            for (int cc = 0; cc < 4; cc++) o[rr][cc] += pv[rr] * vv[cc];
    }
#pragma unroll
    for (int rr = 0; rr < 4; rr++)
#pragma unroll
        for (int cc = 0; cc < 4; cc++)
            O[(rowbase + qt * 64 + r0 + rr) * DIMM + col0 + tx + 16 * cc] = o[rr][cc];
}

// ---------------- GEGLU elementwise ----------------
__global__ __launch_bounds__(256) void geglu_kernel(
    const float* __restrict__ proj, const float* __restrict__ b1,
    float* __restrict__ h)
{
    size_t idx = (size_t)blockIdx.x * 256 + threadIdx.x; // float4-groups over [T_TOK,4096]
    size_t t = idx >> 10;
    int j4 = (int)(idx & 1023) << 2;
    float4 a4 = *(const float4*)(proj + t * 8192 + j4);
    float4 g4 = *(const float4*)(proj + t * 8192 + 4096 + j4);
    float4 ba = *(const float4*)(b1 + j4);
    float4 bg = *(const float4*)(b1 + 4096 + j4);
    float4 r;
    {
        float a = a4.x + ba.x, g = g4.x + bg.x;
        r.x = a * 0.5f * g * (1.f + erff(g * 0.70710678f));
    }
    {
        float a = a4.y + ba.y, g = g4.y + bg.y;
        r.y = a * 0.5f * g * (1.f + erff(g * 0.70710678f));
    }
    {
        float a = a4.z + ba.z, g = g4.z + bg.z;
        r.z = a * 0.5f * g * (1.f + erff(g * 0.70710678f));
    }
    {
        float a = a4.w + ba.w, g = g4.w + bg.w;
        r.w = a * 0.5f * g * (1.f + erff(g * 0.70710678f));
    }
    *(float4*)(h + t * 4096 + j4) = r;
}

// ---------------- launch ----------------
#define SELF_SMEM  ((64 * 64 + 3 * 64 * SKD) * 4)
#define CROSS_SMEM ((64 * 64 + 2 * 80 * SKD + 64 * 80) * 4)

extern "C" void kernel_launch(void* const* d_in, const int* in_sizes, int n_in,
                              void* d_out, int out_size)
{
    const float* x    = (const float*)d_in[0];
    const float* ctx  = (const float*)d_in[1];
    const float* Wq1  = (const float*)d_in[2];
    const float* Wk1  = (const float*)d_in[3];
    const float* Wv1  = (const float*)d_in[4];
    const float* Wo1  = (const float*)d_in[5];
    const float* bo1  = (const float*)d_in[6];
    const float* Wq2  = (const float*)d_in[7];
    const float* Wk2  = (const float*)d_in[8];
    const float* Wv2  = (const float*)d_in[9];
    const float* Wo2  = (const float*)d_in[10];
    const float* bo2  = (const float*)d_in[11];
    const float* Wff1 = (const float*)d_in[12];
    const float* bff1 = (const float*)d_in[13];
    const float* Wff2 = (const float*)d_in[14];
    const float* bff2 = (const float*)d_in[15];
    const float* g1   = (const float*)d_in[16];
    const float* be1  = (const float*)d_in[17];
    const float* g2   = (const float*)d_in[18];
    const float* be2  = (const float*)d_in[19];
    const float* g3   = (const float*)d_in[20];
    const float* be3  = (const float*)d_in[21];
    float* out = (float*)d_out;

    float *ln, *q, *k, *v, *attn, *x1, *x2, *ffp, *hb;
    cudaGetSymbolAddress((void**)&ln,   g_ln);
    cudaGetSymbolAddress((void**)&q,    g_q);
    cudaGetSymbolAddress((void**)&k,    g_k);
    cudaGetSymbolAddress((void**)&v,    g_v);
    cudaGetSymbolAddress((void**)&attn, g_attn);
    cudaGetSymbolAddress((void**)&x1,   g_x1);
    cudaGetSymbolAddress((void**)&x2,   g_x2);
    cudaGetSymbolAddress((void**)&ffp,  g_ffp);
    cudaGetSymbolAddress((void**)&hb,   g_h);

    static int attr_done = 0;
    if (!attr_done) {
        cudaFuncSetAttribute(attn_self_kernel,
                             cudaFuncAttributeMaxDynamicSharedMemorySize, SELF_SMEM);
        cudaFuncSetAttribute(attn_cross_kernel,
                             cudaFuncAttributeMaxDynamicSharedMemorySize, CROSS_SMEM);
        attr_done = 1;
    }

    dim3 blk(256);
    dim3 gN1024(DIMM / BN, T_TOK / BM);   // (8, 64)
    dim3 gFF1(8192 / BN, T_TOK / BM);     // (64, 64)
    dim3 gCTX(DIMM / BN, 3);              // M=308 -> 3 row tiles of 128
    dim3 gATT(SEQ / 64, NHEAD, BATCH);

    // ---- block 1: self attention ----
    ln_kernel<<<T_TOK, 256>>>(x, g1, be1, ln);
    gemm_kernel<false, false><<<gN1024, blk>>>(ln, Wq1, 0, 0, q, T_TOK, DIMM, DIMM);
    gemm_kernel<false, false><<<gN1024, blk>>>(ln, Wk1, 0, 0, k, T_TOK, DIMM, DIMM);
    gemm_kernel<false, false><<<gN1024, blk>>>(ln, Wv1, 0, 0, v, T_TOK, DIMM, DIMM);
    attn_self_kernel<<<gATT, blk, SELF_SMEM>>>(q, k, v, attn);
    gemm_kernel<true, true><<<gN1024, blk>>>(attn, Wo1, bo1, x, x1, T_TOK, DIMM, DIMM);

    // ---- block 2: cross attention ----
    ln_kernel<<<T_TOK, 256>>>(x1, g2, be2, ln);
    gemm_kernel<false, false><<<gN1024, blk>>>(ln, Wq2, 0, 0, q, T_TOK, DIMM, DIMM);
    gemm_kernel<false, false><<<gCTX, blk>>>(ctx, Wk2, 0, 0, k, BATCH * NCTX, 768, DIMM);
    gemm_kernel<false, false><<<gCTX, blk>>>(ctx, Wv2, 0, 0, v, BATCH * NCTX, 768, DIMM);
    attn_cross_kernel<<<gATT, blk, CROSS_SMEM>>>(q, k, v, attn);
    gemm_kernel<true, true><<<gN1024, blk>>>(attn, Wo2, bo2, x1, x2, T_TOK, DIMM, DIMM);

    // ---- block 3: GEGLU feed-forward ----
    ln_kernel<<<T_TOK, 256>>>(x2, g3, be3, ln);
    gemm_kernel<false, false><<<gFF1, blk>>>(ln, Wff1, 0, 0, ffp, T_TOK, DIMM, 8192);
    geglu_kernel<<<(T_TOK * 1024) / 256, 256>>>(ffp, bff1, hb);
    gemm_kernel<true, true><<<gN1024, blk>>>(hb, Wff2, bff2, x2, out, T_TOK, FFI, DIMM);
}

// round 17
// speedup vs baseline: 2.4529x; 2.4529x over previous
#include <cuda_runtime.h>
#include <math.h>
#include <stdint.h>

#define T_TOK 8192
#define DIMM  1024
#define NHEAD 16
#define DHEAD 64
#define NCTX  77
#define BATCH 4
#define SEQ   2048
#define FFI   4096

// ---------------- scratch (device globals: allocation-free) ----------------
__device__ float g_ln  [T_TOK * DIMM];
__device__ float g_q   [T_TOK * DIMM];
__device__ float g_k   [T_TOK * DIMM];
__device__ float g_v   [T_TOK * DIMM];
__device__ float g_attn[T_TOK * DIMM];
__device__ float g_x1  [T_TOK * DIMM];
__device__ float g_x2  [T_TOK * DIMM];
__device__ float g_ffp [(size_t)T_TOK * 8192];
__device__ float g_h   [(size_t)T_TOK * FFI];

// ---------------- packed f32x2 helpers ----------------
__device__ __forceinline__ unsigned long long pk2(float x, float y) {
    unsigned long long r;
    asm("mov.b64 %0, {%1,%2};" : "=l"(r) : "f"(x), "f"(y));
    return r;
}
__device__ __forceinline__ unsigned long long f2u(float2 v) {
    unsigned long long r;
    asm("mov.b64 %0, {%1,%2};" : "=l"(r) : "f"(v.x), "f"(v.y));
    return r;
}
__device__ __forceinline__ void fma2(unsigned long long& d, unsigned long long a,
                                     unsigned long long b) {
    asm("fma.rn.f32x2 %0, %1, %2, %0;" : "+l"(d) : "l"(a), "l"(b));
}
__device__ __forceinline__ unsigned long long mul2(unsigned long long a,
                                                   unsigned long long b) {
    unsigned long long r;
    asm("mul.rn.f32x2 %0, %1, %2;" : "=l"(r) : "l"(a), "l"(b));
    return r;
}
__device__ __forceinline__ float2 u2f(unsigned long long v) {
    float2 r;
    asm("mov.b64 {%0,%1}, %2;" : "=f"(r.x), "=f"(r.y) : "l"(v));
    return r;
}

__device__ __forceinline__ uint32_t smem_u32(const void* p) {
    uint32_t a;
    asm("{ .reg .u64 t; cvta.to.shared.u64 t, %1; cvt.u32.u64 %0, t; }"
        : "=r"(a) : "l"(p));
    return a;
}
// pack two fp32 -> bf16x2, low half = e0
__device__ __forceinline__ uint32_t pkbf(float e0, float e1) {
    uint32_t r;
    asm("cvt.rn.bf16x2.f32 %0, %1, %2;" : "=r"(r) : "f"(e1), "f"(e0));
    return r;
}

// ---------------- mma.sync + ldmatrix (arch-portable tensor core) ----------
__device__ __forceinline__ void mma_bf16(float* c, uint32_t a0, uint32_t a1,
                                         uint32_t a2, uint32_t a3,
                                         uint32_t b0, uint32_t b1) {
    asm volatile(
        "mma.sync.aligned.m16n8k16.row.col.f32.bf16.bf16.f32 "
        "{%0,%1,%2,%3}, {%4,%5,%6,%7}, {%8,%9}, {%0,%1,%2,%3};"
        : "+f"(c[0]), "+f"(c[1]), "+f"(c[2]), "+f"(c[3])
        : "r"(a0), "r"(a1), "r"(a2), "r"(a3), "r"(b0), "r"(b1));
}
__device__ __forceinline__ void ldsm4(uint32_t* r, uint32_t addr) {
    asm volatile("ldmatrix.sync.aligned.m8n8.x4.shared.b16 {%0,%1,%2,%3}, [%4];"
                 : "=r"(r[0]), "=r"(r[1]), "=r"(r[2]), "=r"(r[3]) : "r"(addr));
}
__device__ __forceinline__ void ldsm2(uint32_t* r, uint32_t addr) {
    asm volatile("ldmatrix.sync.aligned.m8n8.x2.shared.b16 {%0,%1}, [%2];"
                 : "=r"(r[0]), "=r"(r[1]) : "r"(addr));
}

// ---------------- LayerNorm ----------------
__global__ __launch_bounds__(256) void ln_kernel(
    const float* __restrict__ x, const float* __restrict__ g,
    const float* __restrict__ be, float* __restrict__ out)
{
    __shared__ float redS[8], redQ[8];
    int row = blockIdx.x, tid = threadIdx.x;
    float4 v = ((const float4*)(x + (size_t)row * DIMM))[tid];
    float s = v.x + v.y + v.z + v.w;
    float q = v.x * v.x + v.y * v.y + v.z * v.z + v.w * v.w;
#pragma unroll
    for (int off = 16; off > 0; off >>= 1) {
        s += __shfl_xor_sync(0xffffffffu, s, off);
        q += __shfl_xor_sync(0xffffffffu, q, off);
    }
    if ((tid & 31) == 0) { redS[tid >> 5] = s; redQ[tid >> 5] = q; }
    __syncthreads();
    float ts = 0.f, tq = 0.f;
#pragma unroll
    for (int w = 0; w < 8; w++) { ts += redS[w]; tq += redQ[w]; }
    float mean = ts * (1.f / 1024.f);
    float var  = tq * (1.f / 1024.f) - mean * mean;
    float rstd = rsqrtf(var + 1e-5f);
    float4 gg = ((const float4*)g)[tid];
    float4 bb = ((const float4*)be)[tid];
    float4 o;
    o.x = (v.x - mean) * rstd * gg.x + bb.x;
    o.y = (v.y - mean) * rstd * gg.y + bb.y;
    o.z = (v.z - mean) * rstd * gg.z + bb.z;
    o.w = (v.w - mean) * rstd * gg.w + bb.w;
    ((float4*)(out + (size_t)row * DIMM))[tid] = o;
}

// ============ HMMA GEMM: C[MxN] = A[MxK] @ B[KxN] (+bias)(+res) =============
// 128x128 CTA tile, 8 warps (2x4), warp tile 64x32, K-chunk 32.
// Split-bf16: acc += Ahi*Bhi + Ahi*Blo + Alo*Bhi (fp32 accum).
// Smem row stride 80B (40 bf16): 16B aligned, conflict-free ldmatrix phases.
#define GSTRIDE 80
#define SA_HI 0
#define SA_LO 10240
#define SB_HI 20480
#define SB_LO 30720
#define STG   40960
#define TCG_SMEM (2 * STG)

template <bool BIAS, bool RES>
__global__ __launch_bounds__(256, 1)
void tc_gemm(const float* __restrict__ A, const float* __restrict__ B,
             const float* __restrict__ bias, const float* __restrict__ res,
             float* __restrict__ C, int M, int K, int N)
{
    extern __shared__ char smem[];
    int tid = threadIdx.x, lane = tid & 31, wid = tid >> 5;
    int wr = wid >> 2, wc = wid & 3;
    int m0 = blockIdx.y * 128, n0 = blockIdx.x * 128;

    float acc[4][4][4];
#pragma unroll
    for (int i = 0; i < 4; i++)
#pragma unroll
        for (int j = 0; j < 4; j++)
#pragma unroll
            for (int l = 0; l < 4; l++) acc[i][j][l] = 0.f;

    // loader indices
    int aR = tid >> 3;              // A: rows aR, +32, +64, +96; k-quad tid&7
    int aK = (tid & 7) * 4;
    int bN = tid & 127;             // B: col n; k-offsets (tid>>7)*4 + 8*t
    int bK = (tid >> 7) * 4;

    float4 aP[4];
    float  bP[4][4];
    int NC = K / 32;

    // prefetch chunk 0
#pragma unroll
    for (int t = 0; t < 4; t++) {
        int m = m0 + aR + 32 * t;
        aP[t] = (m < M) ? *(const float4*)(A + (size_t)m * K + aK)
                        : make_float4(0.f, 0.f, 0.f, 0.f);
    }
#pragma unroll
    for (int t = 0; t < 4; t++) {
        const float* bp = B + (size_t)(bK + 8 * t) * N + n0 + bN;
        bP[t][0] = bp[0]; bP[t][1] = bp[N];
        bP[t][2] = bp[2 * (size_t)N]; bP[t][3] = bp[3 * (size_t)N];
    }

    for (int c = 0; c < NC; c++) {
        char* st = smem + (c & 1) * STG;
        // ---- STS: convert fp32 -> bf16 hi/lo ----
#pragma unroll
        for (int t = 0; t < 4; t++) {
            int row = aR + 32 * t;
            uint32_t off = (uint32_t)(row * GSTRIDE + (tid & 7) * 8);
            float4 a = aP[t];
            uint32_t h01 = pkbf(a.x, a.y), h23 = pkbf(a.z, a.w);
            float fx = __uint_as_float(h01 << 16);
            float fy = __uint_as_float(h01 & 0xFFFF0000u);
            float fz = __uint_as_float(h23 << 16);
            float fw = __uint_as_float(h23 & 0xFFFF0000u);
            uint32_t l01 = pkbf(a.x - fx, a.y - fy);
            uint32_t l23 = pkbf(a.z - fz, a.w - fw);
            *(uint2*)(st + SA_HI + off) = make_uint2(h01, h23);
            *(uint2*)(st + SA_LO + off) = make_uint2(l01, l23);
        }
#pragma unroll
        for (int t = 0; t < 4; t++) {
            int kq = (tid >> 7) + 2 * t;
            uint32_t off = (uint32_t)(bN * GSTRIDE + kq * 8);
            float b0 = bP[t][0], b1 = bP[t][1], b2 = bP[t][2], b3 = bP[t][3];
            uint32_t h01 = pkbf(b0, b1), h23 = pkbf(b2, b3);
            float f0 = __uint_as_float(h01 << 16);
            float f1 = __uint_as_float(h01 & 0xFFFF0000u);
            float f2 = __uint_as_float(h23 << 16);
            float f3 = __uint_as_float(h23 & 0xFFFF0000u);
            uint32_t l01 = pkbf(b0 - f0, b1 - f1);
            uint32_t l23 = pkbf(b2 - f2, b3 - f3);
            *(uint2*)(st + SB_HI + off) = make_uint2(h01, h23);
            *(uint2*)(st + SB_LO + off) = make_uint2(l01, l23);
        }
        __syncthreads();

        // ---- prefetch next chunk (LDG latency hidden under mma) ----
        if (c + 1 < NC) {
            int kb = (c + 1) * 32;
#pragma unroll
            for (int t = 0; t < 4; t++) {
                int m = m0 + aR + 32 * t;
                aP[t] = (m < M) ? *(const float4*)(A + (size_t)m * K + kb + aK)
                                : make_float4(0.f, 0.f, 0.f, 0.f);
            }
#pragma unroll
            for (int t = 0; t < 4; t++) {
                const float* bp = B + (size_t)(kb + bK + 8 * t) * N + n0 + bN;
                bP[t][0] = bp[0]; bP[t][1] = bp[N];
                bP[t][2] = bp[2 * (size_t)N]; bP[t][3] = bp[3 * (size_t)N];
            }
        }

        // ---- compute: 2 k-steps of k16, 3 split passes ----
        uint32_t sAh = smem_u32(st + SA_HI);
        uint32_t sAl = smem_u32(st + SA_LO);
        uint32_t sBh = smem_u32(st + SB_HI);
        uint32_t sBl = smem_u32(st + SB_LO);
        uint32_t aOff = (uint32_t)((wr * 64 + (lane & 15)) * GSTRIDE +
                                   (lane >> 4) * 16);
        uint32_t bOff = (uint32_t)((wc * 32 + (lane & 7)) * GSTRIDE +
                                   ((lane >> 3) & 1) * 16);
#pragma unroll
        for (int ks = 0; ks < 2; ks++) {
            uint32_t ko = ks * 32;
            uint32_t ah[4][4], al[4][4], bh[4][2], bl[4][2];
#pragma unroll
            for (int mt = 0; mt < 4; mt++) {
                uint32_t ad = aOff + mt * (16 * GSTRIDE) + ko;
                ldsm4(ah[mt], sAh + ad);
                ldsm4(al[mt], sAl + ad);
            }
#pragma unroll
            for (int nt = 0; nt < 4; nt++) {
                uint32_t bd = bOff + nt * (8 * GSTRIDE) + ko;
                ldsm2(bh[nt], sBh + bd);
                ldsm2(bl[nt], sBl + bd);
            }
#pragma unroll
            for (int mt = 0; mt < 4; mt++)
#pragma unroll
                for (int nt = 0; nt < 4; nt++)
                    mma_bf16(acc[mt][nt], ah[mt][0], ah[mt][1], ah[mt][2],
                             ah[mt][3], bh[nt][0], bh[nt][1]);
#pragma unroll
            for (int mt = 0; mt < 4; mt++)
#pragma unroll
                for (int nt = 0; nt < 4; nt++)
                    mma_bf16(acc[mt][nt], ah[mt][0], ah[mt][1], ah[mt][2],
                             ah[mt][3], bl[nt][0], bl[nt][1]);
#pragma unroll
            for (int mt = 0; mt < 4; mt++)
#pragma unroll
                for (int nt = 0; nt < 4; nt++)
                    mma_bf16(acc[mt][nt], al[mt][0], al[mt][1], al[mt][2],
                             al[mt][3], bh[nt][0], bh[nt][1]);
        }
    }

    // ---- epilogue ----
#pragma unroll
    for (int mt = 0; mt < 4; mt++) {
#pragma unroll
        for (int nt = 0; nt < 4; nt++) {
            int m = m0 + wr * 64 + mt * 16 + (lane >> 2);
            int n = n0 + wc * 32 + nt * 8 + (lane & 3) * 2;
            float2 v0 = make_float2(acc[mt][nt][0], acc[mt][nt][1]);
            float2 v1 = make_float2(acc[mt][nt][2], acc[mt][nt][3]);
            if (BIAS) {
                float2 bb = *(const float2*)(bias + n);
                v0.x += bb.x; v0.y += bb.y;
                v1.x += bb.x; v1.y += bb.y;
            }
            if (m < M) {
                if (RES) {
                    float2 rr = *(const float2*)(res + (size_t)m * N + n);
                    v0.x += rr.x; v0.y += rr.y;
                }
                *(float2*)(C + (size_t)m * N + n) = v0;
            }
            if (m + 8 < M) {
                if (RES) {
                    float2 rr = *(const float2*)(res + (size_t)(m + 8) * N + n);
                    v1.x += rr.x; v1.y += rr.y;
                }
                *(float2*)(C + (size_t)(m + 8) * N + n) = v1;
            }
        }
    }
}

// ---------------- self attention (flash, 64q x 64k tiles, fp32) -------------
#define SKD 66

__global__ __launch_bounds__(256) void attn_self_kernel(
    const float* __restrict__ Q, const float* __restrict__ K,
    const float* __restrict__ V, float* __restrict__ O)
{
    extern __shared__ float sm[];
    float (*Qs)[64]  = (float(*)[64])sm;
    float (*Ks)[SKD] = (float(*)[SKD])(sm + 64 * 64);
    float (*Vs)[SKD] = (float(*)[SKD])(sm + 64 * 64 + 64 * SKD);
    float (*Ps)[SKD] = (float(*)[SKD])(sm + 64 * 64 + 2 * 64 * SKD);
    int tid = threadIdx.x;
    int tx = tid & 15, ty = tid >> 4;
    int b = blockIdx.z, h = blockIdx.y, qt = blockIdx.x;
    size_t rowbase = (size_t)b * SEQ;
    int col0 = h * DHEAD;

    for (int i = tid; i < 64 * 16; i += 256) {
        int r = i >> 4, dp = (i & 15) << 2;
        *(float4*)&Qs[r][dp] =
            *(const float4*)(Q + (rowbase + qt * 64 + r) * DIMM + col0 + dp);
    }
    int r0 = ty * 4;
    unsigned long long o2[4][4];
#pragma unroll
    for (int i = 0; i < 4; i++)
#pragma unroll
        for (int j = 0; j < 4; j++) o2[i][j] = 0ULL;
    float mrow[4] = {-1e30f, -1e30f, -1e30f, -1e30f};
    float lrow[4] = {0.f, 0.f, 0.f, 0.f};
    const float scale = 0.125f;

    for (int kt = 0; kt < SEQ / 64; kt++) {
        __syncthreads();
        for (int i = tid; i < 64 * 16; i += 256) {
            int c = i >> 4, dp = (i & 15) << 2;
            float4 kv = *(const float4*)(K + (rowbase + kt * 64 + c) * DIMM + col0 + dp);
            Ks[c][dp + 0] = kv.x; Ks[c][dp + 1] = kv.y;
            Ks[c][dp + 2] = kv.z; Ks[c][dp + 3] = kv.w;
            float4 vv = *(const float4*)(V + (rowbase + kt * 64 + c) * DIMM + col0 + dp);
            Vs[dp + 0][c] = vv.x; Vs[dp + 1][c] = vv.y;
            Vs[dp + 2][c] = vv.z; Vs[dp + 3][c] = vv.w;
        }
        __syncthreads();

        unsigned long long s2[4][4];
#pragma unroll
        for (int i = 0; i < 4; i++)
#pragma unroll
            for (int j = 0; j < 4; j++) s2[i][j] = 0ULL;
        for (int d2 = 0; d2 < 32; d2++) {
            unsigned long long q2[4], k2[4];
#pragma unroll
            for (int rr = 0; rr < 4; rr++)
                q2[rr] = f2u(*(const float2*)&Qs[r0 + rr][2 * d2]);
#pragma unroll
            for (int cc = 0; cc < 4; cc++)
                k2[cc] = f2u(*(const float2*)&Ks[tx + 16 * cc][2 * d2]);
#pragma unroll
            for (int rr = 0; rr < 4; rr++)
#pragma unroll
                for (int cc = 0; cc < 4; cc++) fma2(s2[rr][cc], q2[rr], k2[cc]);
        }

#pragma unroll
        for (int rr = 0; rr < 4; rr++) {
            float sv[4];
#pragma unroll
            for (int cc = 0; cc < 4; cc++) {
                float2 t = u2f(s2[rr][cc]);
                sv[cc] = (t.x + t.y) * scale;
            }
            float mx = fmaxf(fmaxf(sv[0], sv[1]), fmaxf(sv[2], sv[3]));
#pragma unroll
            for (int off = 8; off > 0; off >>= 1)
                mx = fmaxf(mx, __shfl_xor_sync(0xffffffffu, mx, off));
            float mnew  = fmaxf(mrow[rr], mx);
            float alpha = __expf(mrow[rr] - mnew);
            mrow[rr] = mnew;
            float psum = 0.f;
#pragma unroll
            for (int cc = 0; cc < 4; cc++) {
                float p = __expf(sv[cc] - mnew);
                Ps[r0 + rr][tx + 16 * cc] = p;
                psum += p;
            }
#pragma unroll
            for (int off = 8; off > 0; off >>= 1)
                psum += __shfl_xor_sync(0xffffffffu, psum, off);
            lrow[rr] = lrow[rr] * alpha + psum;
            unsigned long long a2 = pk2(alpha, alpha);
#pragma unroll
            for (int cc = 0; cc < 4; cc++) o2[rr][cc] = mul2(a2, o2[rr][cc]);
        }
        __syncthreads();

        for (int j2 = 0; j2 < 32; j2++) {
            unsigned long long p2[4], v2[4];
#pragma unroll
            for (int rr = 0; rr < 4; rr++)
                p2[rr] = f2u(*(const float2*)&Ps[r0 + rr][2 * j2]);
#pragma unroll
            for (int cc = 0; cc < 4; cc++)
                v2[cc] = f2u(*(const float2*)&Vs[tx + 16 * cc][2 * j2]);
#pragma unroll
            for (int rr = 0; rr < 4; rr++)
#pragma unroll
                for (int cc = 0; cc < 4; cc++) fma2(o2[rr][cc], p2[rr], v2[cc]);
        }
    }

#pragma unroll
    for (int rr = 0; rr < 4; rr++) {
        float inv = 1.f / lrow[rr];
#pragma unroll
        for (int cc = 0; cc < 4; cc++) {
            float2 t = u2f(o2[rr][cc]);
            O[(rowbase + qt * 64 + r0 + rr) * DIMM + col0 + tx + 16 * cc] =
                (t.x + t.y) * inv;
        }
    }
}

// ---------------- cross attention (77 keys, one pass) ----------------
__global__ __launch_bounds__(256) void attn_cross_kernel(
    const float* __restrict__ Q, const float* __restrict__ K,
    const float* __restrict__ V, float* __restrict__ O)
{
    extern __shared__ float sm[];
    float (*Qs)[64]  = (float(*)[64])sm;
    float (*Ks)[SKD] = (float(*)[SKD])(sm + 64 * 64);
    float (*Vs)[SKD] = (float(*)[SKD])(sm + 64 * 64 + 80 * SKD);
    float (*Ps)[80]  = (float(*)[80])(sm + 64 * 64 + 2 * 80 * SKD);
    int tid = threadIdx.x;
    int tx = tid & 15, ty = tid >> 4;
    int b = blockIdx.z, h = blockIdx.y, qt = blockIdx.x;
    size_t rowbase = (size_t)b * SEQ;
    int col0 = h * DHEAD;

    for (int i = tid; i < 64 * 16; i += 256) {
        int r = i >> 4, dp = (i & 15) << 2;
        *(float4*)&Qs[r][dp] =
            *(const float4*)(Q + (rowbase + qt * 64 + r) * DIMM + col0 + dp);
    }
    for (int i = tid; i < 80 * 16; i += 256) {
        int j = i >> 4, dp = (i & 15) << 2;
        float4 kv = make_float4(0.f, 0.f, 0.f, 0.f);
        float4 vv = make_float4(0.f, 0.f, 0.f, 0.f);
        if (j < NCTX) {
            kv = *(const float4*)(K + ((size_t)b * NCTX + j) * DIMM + col0 + dp);
            vv = *(const float4*)(V + ((size_t)b * NCTX + j) * DIMM + col0 + dp);
        }
        Ks[j][dp + 0] = kv.x; Ks[j][dp + 1] = kv.y;
        Ks[j][dp + 2] = kv.z; Ks[j][dp + 3] = kv.w;
        Vs[j][dp + 0] = vv.x; Vs[j][dp + 1] = vv.y;
        Vs[j][dp + 2] = vv.z; Vs[j][dp + 3] = vv.w;
    }
    __syncthreads();

    int r0 = ty * 4;
    float s[4][5];
#pragma unroll
    for (int rr = 0; rr < 4; rr++)
#pragma unroll
        for (int jj = 0; jj < 5; jj++) s[rr][jj] = 0.f;

    for (int d = 0; d < 64; d++) {
        float qv[4], kv[5];
#pragma unroll
        for (int rr = 0; rr < 4; rr++) qv[rr] = Qs[r0 + rr][d];
#pragma unroll
        for (int jj = 0; jj < 5; jj++) kv[jj] = Ks[tx + 16 * jj][d];
#pragma unroll
        for (int rr = 0; rr < 4; rr++)
#pragma unroll
            for (int jj = 0; jj < 5; jj++) s[rr][jj] += qv[rr] * kv[jj];
    }

    const float scale = 0.125f;
#pragma unroll
    for (int rr = 0; rr < 4; rr++) {
        float mx = -1e30f;
#pragma unroll
        for (int jj = 0; jj < 5; jj++) {
            int c = tx + 16 * jj;
            s[rr][jj] *= scale;
            if (c < NCTX) mx = fmaxf(mx, s[rr][jj]);
        }
#pragma unroll
        for (int off = 8; off > 0; off >>= 1)
            mx = fmaxf(mx, __shfl_xor_sync(0xffffffffu, mx, off));
        float sum = 0.f, p[5];
#pragma unroll
        for (int jj = 0; jj < 5; jj++) {
            int c = tx + 16 * jj;
            p[jj] = (c < NCTX) ? __expf(s[rr][jj] - mx) : 0.f;
            sum += p[jj];
        }
#pragma unroll
        for (int off = 8; off > 0; off >>= 1)
            sum += __shfl_xor_sync(0xffffffffu, sum, off);
        float inv = 1.f / sum;
#pragma unroll
        for (int jj = 0; jj < 5; jj++) Ps[r0 + rr][tx + 16 * jj] = p[jj] * inv;
    }
    __syncthreads();

    float o[4][4];
#pragma unroll
    for (int rr = 0; rr < 4; rr++)
#pragma unroll
        for (int cc = 0; cc < 4; cc++) o[rr][cc] = 0.f;
    for (int j = 0; j < NCTX; j++) {
        float pv[4], vv[4];
#pragma unroll
        for (int rr = 0; rr < 4; rr++) pv[rr] = Ps[r0 + rr][j];
#pragma unroll
        for (int cc = 0; cc < 4; cc++) vv[cc] = Vs[j][tx + 16 * cc];
#pragma unroll
        for (int rr = 0; rr < 4; rr++)
#pragma unroll
            for (int cc = 0; cc < 4; cc++) o[rr][cc] += pv[rr] * vv[cc];
    }
#pragma unroll
    for (int rr = 0; rr < 4; rr++)
#pragma unroll
        for (int cc = 0; cc < 4; cc++)
            O[(rowbase + qt * 64 + r0 + rr) * DIMM + col0 + tx + 16 * cc] = o[rr][cc];
}

// ---------------- GEGLU elementwise ----------------
__global__ __launch_bounds__(256) void geglu_kernel(
    const float* __restrict__ proj, const float* __restrict__ b1,
    float* __restrict__ h)
{
    size_t idx = (size_t)blockIdx.x * 256 + threadIdx.x;
    size_t t = idx >> 10;
    int j4 = (int)(idx & 1023) << 2;
    float4 a4 = *(const float4*)(proj + t * 8192 + j4);
    float4 g4 = *(const float4*)(proj + t * 8192 + 4096 + j4);
    float4 ba = *(const float4*)(b1 + j4);
    float4 bg = *(const float4*)(b1 + 4096 + j4);
    float4 r;
    {
        float a = a4.x + ba.x, g = g4.x + bg.x;
        r.x = a * 0.5f * g * (1.f + erff(g * 0.70710678f));
    }
    {
        float a = a4.y + ba.y, g = g4.y + bg.y;
        r.y = a * 0.5f * g * (1.f + erff(g * 0.70710678f));
    }
    {
        float a = a4.z + ba.z, g = g4.z + bg.z;
        r.z = a * 0.5f * g * (1.f + erff(g * 0.70710678f));
    }
    {
        float a = a4.w + ba.w, g = g4.w + bg.w;
        r.w = a * 0.5f * g * (1.f + erff(g * 0.70710678f));
    }
    *(float4*)(h + t * 4096 + j4) = r;
}

// ---------------- launch ----------------
#define SELF_SMEM  ((64 * 64 + 3 * 64 * SKD) * 4)
#define CROSS_SMEM ((64 * 64 + 2 * 80 * SKD + 64 * 80) * 4)

extern "C" void kernel_launch(void* const* d_in, const int* in_sizes, int n_in,
                              void* d_out, int out_size)
{
    const float* x    = (const float*)d_in[0];
    const float* ctx  = (const float*)d_in[1];
    const float* Wq1  = (const float*)d_in[2];
    const float* Wk1  = (const float*)d_in[3];
    const float* Wv1  = (const float*)d_in[4];
    const float* Wo1  = (const float*)d_in[5];
    const float* bo1  = (const float*)d_in[6];
    const float* Wq2  = (const float*)d_in[7];
    const float* Wk2  = (const float*)d_in[8];
    const float* Wv2  = (const float*)d_in[9];
    const float* Wo2  = (const float*)d_in[10];
    const float* bo2  = (const float*)d_in[11];
    const float* Wff1 = (const float*)d_in[12];
    const float* bff1 = (const float*)d_in[13];
    const float* Wff2 = (const float*)d_in[14];
    const float* bff2 = (const float*)d_in[15];
    const float* g1   = (const float*)d_in[16];
    const float* be1  = (const float*)d_in[17];
    const float* g2   = (const float*)d_in[18];
    const float* be2  = (const float*)d_in[19];
    const float* g3   = (const float*)d_in[20];
    const float* be3  = (const float*)d_in[21];
    float* out = (float*)d_out;

    float *ln, *q, *k, *v, *attn, *x1, *x2, *ffp, *hb;
    cudaGetSymbolAddress((void**)&ln,   g_ln);
    cudaGetSymbolAddress((void**)&q,    g_q);
    cudaGetSymbolAddress((void**)&k,    g_k);
    cudaGetSymbolAddress((void**)&v,    g_v);
    cudaGetSymbolAddress((void**)&attn, g_attn);
    cudaGetSymbolAddress((void**)&x1,   g_x1);
    cudaGetSymbolAddress((void**)&x2,   g_x2);
    cudaGetSymbolAddress((void**)&ffp,  g_ffp);
    cudaGetSymbolAddress((void**)&hb,   g_h);

    static int attr_done = 0;
    if (!attr_done) {
        cudaFuncSetAttribute(attn_self_kernel,
                             cudaFuncAttributeMaxDynamicSharedMemorySize, SELF_SMEM);
        cudaFuncSetAttribute(attn_cross_kernel,
                             cudaFuncAttributeMaxDynamicSharedMemorySize, CROSS_SMEM);
        cudaFuncSetAttribute(tc_gemm<false, false>,
                             cudaFuncAttributeMaxDynamicSharedMemorySize, TCG_SMEM);
        cudaFuncSetAttribute(tc_gemm<true, true>,
                             cudaFuncAttributeMaxDynamicSharedMemorySize, TCG_SMEM);
        attr_done = 1;
    }

    dim3 blk(256);
    dim3 gN1024(8, 64);    // N=1024, M=8192
    dim3 gFF1(64, 64);     // N=8192, M=8192
    dim3 gCTX(8, 3);       // N=1024, M=308
    dim3 gATT(SEQ / 64, NHEAD, BATCH);

    // ---- block 1: self attention ----
    ln_kernel<<<T_TOK, 256>>>(x, g1, be1, ln);
    tc_gemm<false, false><<<gN1024, blk, TCG_SMEM>>>(ln, Wq1, 0, 0, q, T_TOK, DIMM, DIMM);
    tc_gemm<false, false><<<gN1024, blk, TCG_SMEM>>>(ln, Wk1, 0, 0, k, T_TOK, DIMM, DIMM);
    tc_gemm<false, false><<<gN1024, blk, TCG_SMEM>>>(ln, Wv1, 0, 0, v, T_TOK, DIMM, DIMM);
    attn_self_kernel<<<gATT, blk, SELF_SMEM>>>(q, k, v, attn);
    tc_gemm<true, true><<<gN1024, blk, TCG_SMEM>>>(attn, Wo1, bo1, x, x1, T_TOK, DIMM, DIMM);

    // ---- block 2: cross attention ----
    ln_kernel<<<T_TOK, 256>>>(x1, g2, be2, ln);
    tc_gemm<false, false><<<gN1024, blk, TCG_SMEM>>>(ln, Wq2, 0, 0, q, T_TOK, DIMM, DIMM);
    tc_gemm<false, false><<<gCTX, blk, TCG_SMEM>>>(ctx, Wk2, 0, 0, k, BATCH * NCTX, 768, DIMM);
    tc_gemm<false, false><<<gCTX, blk, TCG_SMEM>>>(ctx, Wv2, 0, 0, v, BATCH * NCTX, 768, DIMM);
    attn_cross_kernel<<<gATT, blk, CROSS_SMEM>>>(q, k, v, attn);
    tc_gemm<true, true><<<gN1024, blk, TCG_SMEM>>>(attn, Wo2, bo2, x1, x2, T_TOK, DIMM, DIMM);

    // ---- block 3: GEGLU feed-forward ----
    ln_kernel<<<T_TOK, 256>>>(x2, g3, be3, ln);
    tc_gemm<false, false><<<gFF1, blk, TCG_SMEM>>>(ln, Wff1, 0, 0, ffp, T_TOK, DIMM, 8192);
    geglu_kernel<<<(T_TOK * 1024) / 256, 256>>>(ffp, bff1, hb);
    tc_gemm<true, true><<<gN1024, blk, TCG_SMEM>>>(hb, Wff2, bff2, x2, out, T_TOK, FFI, DIMM);
}